// round 1
// baseline (speedup 1.0000x reference)
#include <cuda_runtime.h>
#include <math.h>

#define NN   50000
#define NE   800000
#define NE2  850000     // NE + NN self loops
#define NG   64
#define IND  128
#define HIDC 32
#define HEADS 4
#define EDIM 8
#define OUTD 10
#define HD1  128        // HEADS*HIDC

// ---------------- scratch (static device globals; no allocation) ----------------
__device__ float    d_loop[NN*EDIM];      // loop attr sums -> loop attr
__device__ float    d_cnt[NN];
__device__ float    d_h1[NN*HD1];
__device__ float    d_als1[NN*HEADS];
__device__ float    d_ald1[NN*HEADS];
__device__ float    d_ae1[NE2*HEADS];
__device__ float    d_alpha1[NE2*HEADS];
__device__ unsigned d_m1[NN*HEADS];
__device__ float    d_den1[NN*HEADS];
__device__ float    d_out1[NN*HD1];
__device__ float    d_h2[NN*HIDC];
__device__ float    d_als2[NN];
__device__ float    d_ald2[NN];
__device__ float    d_ae2[NE2];
__device__ float    d_alpha2[NE2];
__device__ unsigned d_m2[NN];
__device__ float    d_den2[NN];
__device__ float    d_out2[NN*HIDC];
__device__ float    d_gsum[NG*HIDC];
__device__ float    d_gcnt[NG];
__device__ float    d_M1[EDIM*HEADS];
__device__ float    d_M2[EDIM];

// ---------------- helpers ----------------
__device__ __forceinline__ unsigned fenc(float f) {
    unsigned u = __float_as_uint(f);
    return (u & 0x80000000u) ? ~u : (u | 0x80000000u);
}
__device__ __forceinline__ float fdec(unsigned u) {
    return (u & 0x80000000u) ? __uint_as_float(u & 0x7FFFFFFFu) : __uint_as_float(~u);
}
__device__ __forceinline__ float lrelu(float a) { return a > 0.f ? a : 0.2f * a; }
__device__ __forceinline__ float eluf(float a)  { return a > 0.f ? a : expm1f(a); }

#define ENC_NEGINF 0x007FFFFFu

// ---------------- init: zero accumulators, set maxes to -inf ----------------
__global__ void init_kernel() {
    int i = blockIdx.x * blockDim.x + threadIdx.x;
    if (i < NN*HD1)   d_out1[i] = 0.f;
    if (i < NN*HIDC)  d_out2[i] = 0.f;
    if (i < NN*EDIM)  d_loop[i] = 0.f;
    if (i < NN*HEADS) { d_den1[i] = 0.f; d_m1[i] = ENC_NEGINF; }
    if (i < NN)       { d_cnt[i] = 0.f; d_den2[i] = 0.f; d_m2[i] = ENC_NEGINF; }
    if (i < NG*HIDC)  d_gsum[i] = 0.f;
    if (i < NG)       d_gcnt[i] = 0.f;
}

// ---------------- precompute edge-attention projection matrices ----------------
// M1[d][h] = sum_c We1[d, h*32+c] * att_e1[h, c];  M2[d] = sum_c We2[d,c]*att_e2[c]
__global__ void computeM_kernel(const float* __restrict__ We1, const float* __restrict__ ae1,
                                const float* __restrict__ We2, const float* __restrict__ ae2) {
    int t = threadIdx.x;
    if (t < 32) {
        int d = t >> 2, h = t & 3;
        float s = 0.f;
        for (int c = 0; c < 32; c++) s += We1[d*128 + h*32 + c] * ae1[h*32 + c];
        d_M1[d*4 + h] = s;
    } else if (t < 40) {
        int d = t - 32;
        float s = 0.f;
        for (int c = 0; c < 32; c++) s += We2[d*32 + c] * ae2[c];
        d_M2[d] = s;
    }
}

// ---------------- self-loop attr: mean of incoming edge_attr ----------------
__global__ void loop_accum_kernel(const int* __restrict__ ei, const float* __restrict__ eattr) {
    int e = blockIdx.x * blockDim.x + threadIdx.x;
    if (e >= NE) return;
    int d = ei[NE + e];
    atomicAdd(&d_cnt[d], 1.f);
    float4 a = *(const float4*)&eattr[e*8];
    float4 b = *(const float4*)&eattr[e*8 + 4];
    atomicAdd((float4*)&d_loop[d*8], a);
    atomicAdd((float4*)&d_loop[d*8 + 4], b);
}

// finalize loop_attr (mean) and compute self-loop edge-attention terms
__global__ void loop_node_kernel() {
    int n = blockIdx.x * blockDim.x + threadIdx.x;
    if (n >= NN) return;
    float c = fmaxf(d_cnt[n], 1.f);
    float ea[8];
#pragma unroll
    for (int d = 0; d < 8; d++) ea[d] = d_loop[n*8 + d] / c;
#pragma unroll
    for (int h = 0; h < 4; h++) {
        float s = 0.f;
#pragma unroll
        for (int d = 0; d < 8; d++) s += ea[d] * d_M1[d*4 + h];
        d_ae1[(NE + n)*4 + h] = s;
    }
    float s2 = 0.f;
#pragma unroll
    for (int d = 0; d < 8; d++) s2 += ea[d] * d_M2[d];
    d_ae2[NE + n] = s2;
}

// edge-attention terms for real edges
__global__ void ae_edges_kernel(const float* __restrict__ eattr) {
    int e = blockIdx.x * blockDim.x + threadIdx.x;
    if (e >= NE) return;
    float4 a = *(const float4*)&eattr[e*8];
    float4 b = *(const float4*)&eattr[e*8 + 4];
    float ea[8] = {a.x,a.y,a.z,a.w,b.x,b.y,b.z,b.w};
#pragma unroll
    for (int h = 0; h < 4; h++) {
        float s = 0.f;
#pragma unroll
        for (int d = 0; d < 8; d++) s += ea[d] * d_M1[d*4 + h];
        d_ae1[e*4 + h] = s;
    }
    float s2 = 0.f;
#pragma unroll
    for (int d = 0; d < 8; d++) s2 += ea[d] * d_M2[d];
    d_ae2[e] = s2;
}

// ---------------- GEMM1: h1 = x @ W1  (50000x128 @ 128x128) ----------------
__global__ void __launch_bounds__(256) gemm1_kernel(const float* __restrict__ x,
                                                    const float* __restrict__ W1) {
    __shared__ float As[16][128];
    __shared__ float Bs[16][128];
    int tid  = threadIdx.x;
    int row0 = blockIdx.x * 128;
    int ty = tid >> 4, tx = tid & 15;
    float acc[8][8];
#pragma unroll
    for (int i = 0; i < 8; i++)
#pragma unroll
        for (int j = 0; j < 8; j++) acc[i][j] = 0.f;

    for (int k0 = 0; k0 < 128; k0 += 16) {
        {   // load W1 chunk
            int kk = tid >> 5;          // 0..7
            int j  = (tid & 31) << 2;
            *(float4*)&Bs[kk][j]     = *(const float4*)&W1[(k0+kk)*128 + j];
            *(float4*)&Bs[kk+8][j]   = *(const float4*)&W1[(k0+kk+8)*128 + j];
        }
        {   // load x chunk (transposed into As[k][r])
            int rr = tid >> 2;          // 0..63
            int kk = (tid & 3) << 2;    // 0,4,8,12
#pragma unroll
            for (int it = 0; it < 2; it++) {
                int r = rr + it*64;
                int grow = row0 + r;
                float4 v = make_float4(0.f,0.f,0.f,0.f);
                if (grow < NN) v = *(const float4*)&x[grow*128 + k0 + kk];
                As[kk+0][r] = v.x; As[kk+1][r] = v.y; As[kk+2][r] = v.z; As[kk+3][r] = v.w;
            }
        }
        __syncthreads();
#pragma unroll
        for (int kk = 0; kk < 16; kk++) {
            float a[8], b[8];
#pragma unroll
            for (int i = 0; i < 8; i++) a[i] = As[kk][ty*8 + i];
#pragma unroll
            for (int j = 0; j < 8; j++) b[j] = Bs[kk][tx*8 + j];
#pragma unroll
            for (int i = 0; i < 8; i++)
#pragma unroll
                for (int j = 0; j < 8; j++) acc[i][j] = fmaf(a[i], b[j], acc[i][j]);
        }
        __syncthreads();
    }
#pragma unroll
    for (int i = 0; i < 8; i++) {
        int r = row0 + ty*8 + i;
        if (r < NN) {
            float4 v0 = make_float4(acc[i][0], acc[i][1], acc[i][2], acc[i][3]);
            float4 v1 = make_float4(acc[i][4], acc[i][5], acc[i][6], acc[i][7]);
            *(float4*)&d_h1[r*128 + tx*8]     = v0;
            *(float4*)&d_h1[r*128 + tx*8 + 4] = v1;
        }
    }
}

// ---------------- per-node attention logits for conv1 (warp per node) ----------------
__global__ void al1_kernel(const float* __restrict__ as1, const float* __restrict__ ad1) {
    int g = blockIdx.x * blockDim.x + threadIdx.x;
    int n = g >> 5, lane = g & 31;
    if (n >= NN) return;
    float4 h = *(const float4*)&d_h1[n*128 + lane*4];
    float4 s4 = *(const float4*)&as1[lane*4];
    float4 d4 = *(const float4*)&ad1[lane*4];
    float ps = h.x*s4.x + h.y*s4.y + h.z*s4.z + h.w*s4.w;
    float pd = h.x*d4.x + h.y*d4.y + h.z*d4.z + h.w*d4.w;
#pragma unroll
    for (int m = 1; m <= 4; m <<= 1) {
        ps += __shfl_xor_sync(0xffffffffu, ps, m);
        pd += __shfl_xor_sync(0xffffffffu, pd, m);
    }
    if ((lane & 7) == 0) {
        d_als1[n*4 + (lane >> 3)] = ps;
        d_ald1[n*4 + (lane >> 3)] = pd;
    }
}

// ---------------- conv1: alpha + segment max ----------------
__global__ void alpha1_kernel(const int* __restrict__ ei) {
    int e = blockIdx.x * blockDim.x + threadIdx.x;
    if (e >= NE2) return;
    int s, d;
    if (e < NE) { s = ei[e]; d = ei[NE + e]; } else { s = d = e - NE; }
    float4 as = *(const float4*)&d_als1[s*4];
    float4 ad = *(const float4*)&d_ald1[d*4];
    float4 ae = *(const float4*)&d_ae1[e*4];
    float4 al;
    al.x = lrelu(as.x + ad.x + ae.x);
    al.y = lrelu(as.y + ad.y + ae.y);
    al.z = lrelu(as.z + ad.z + ae.z);
    al.w = lrelu(as.w + ad.w + ae.w);
    *(float4*)&d_alpha1[e*4] = al;
    atomicMax(&d_m1[d*4 + 0], fenc(al.x));
    atomicMax(&d_m1[d*4 + 1], fenc(al.y));
    atomicMax(&d_m1[d*4 + 2], fenc(al.z));
    atomicMax(&d_m1[d*4 + 3], fenc(al.w));
}

// ---------------- conv1: exp + denominator ----------------
__global__ void expden1_kernel(const int* __restrict__ ei) {
    int e = blockIdx.x * blockDim.x + threadIdx.x;
    if (e >= NE2) return;
    int d = (e < NE) ? ei[NE + e] : (e - NE);
    float4 al = *(const float4*)&d_alpha1[e*4];
    float4 v;
    v.x = expf(al.x - fdec(d_m1[d*4 + 0]));
    v.y = expf(al.y - fdec(d_m1[d*4 + 1]));
    v.z = expf(al.z - fdec(d_m1[d*4 + 2]));
    v.w = expf(al.w - fdec(d_m1[d*4 + 3]));
    *(float4*)&d_alpha1[e*4] = v;
    atomicAdd(&d_den1[d*4 + 0], v.x);
    atomicAdd(&d_den1[d*4 + 1], v.y);
    atomicAdd(&d_den1[d*4 + 2], v.z);
    atomicAdd(&d_den1[d*4 + 3], v.w);
}

// ---------------- conv1: weighted message scatter (warp per edge) ----------------
__global__ void msg1_kernel(const int* __restrict__ ei) {
    int g = blockIdx.x * blockDim.x + threadIdx.x;
    int e = g >> 5, lane = g & 31;
    if (e >= NE2) return;
    int s, d;
    if (e < NE) { s = ei[e]; d = ei[NE + e]; } else { s = d = e - NE; }
    int head = lane >> 3;
    float w = d_alpha1[e*4 + head] / (d_den1[d*4 + head] + 1e-16f);
    float4 hv = *(const float4*)&d_h1[s*128 + lane*4];
    float4 m  = make_float4(hv.x*w, hv.y*w, hv.z*w, hv.w*w);
    atomicAdd((float4*)&d_out1[d*128 + lane*4], m);
}

// ---------------- GEMM2: h2 = elu(out1 + b1) @ W2  (50000x128 @ 128x32) ----------------
__global__ void __launch_bounds__(256) gemm2_kernel(const float* __restrict__ W2,
                                                    const float* __restrict__ b1) {
    __shared__ float As[32][128];
    __shared__ float Bs[32][32];
    int tid  = threadIdx.x;
    int row0 = blockIdx.x * 128;
    int ty = tid >> 3, tx = tid & 7;   // ty 0..31, tx 0..7
    float acc[4][4];
#pragma unroll
    for (int i = 0; i < 4; i++)
#pragma unroll
        for (int j = 0; j < 4; j++) acc[i][j] = 0.f;

    for (int k0 = 0; k0 < 128; k0 += 32) {
        {   // load W2 chunk
            int kk = tid >> 3, j = (tid & 7) << 2;
            *(float4*)&Bs[kk][j] = *(const float4*)&W2[(k0+kk)*32 + j];
        }
        {   // load A = elu(out1 + b1)
            int rr = tid >> 3;
            int kks = (tid & 7) << 2;
            float4 bb = *(const float4*)&b1[k0 + kks];
#pragma unroll
            for (int it = 0; it < 4; it++) {
                int r = rr + it*32;
                int grow = row0 + r;
                float4 v = make_float4(0.f,0.f,0.f,0.f);
                if (grow < NN) {
                    v = *(const float4*)&d_out1[grow*128 + k0 + kks];
                    v.x = eluf(v.x + bb.x); v.y = eluf(v.y + bb.y);
                    v.z = eluf(v.z + bb.z); v.w = eluf(v.w + bb.w);
                }
                As[kks+0][r] = v.x; As[kks+1][r] = v.y; As[kks+2][r] = v.z; As[kks+3][r] = v.w;
            }
        }
        __syncthreads();
#pragma unroll
        for (int kk = 0; kk < 32; kk++) {
            float a[4], b[4];
#pragma unroll
            for (int i = 0; i < 4; i++) a[i] = As[kk][ty*4 + i];
#pragma unroll
            for (int j = 0; j < 4; j++) b[j] = Bs[kk][tx*4 + j];
#pragma unroll
            for (int i = 0; i < 4; i++)
#pragma unroll
                for (int j = 0; j < 4; j++) acc[i][j] = fmaf(a[i], b[j], acc[i][j]);
        }
        __syncthreads();
    }
#pragma unroll
    for (int i = 0; i < 4; i++) {
        int r = row0 + ty*4 + i;
        if (r < NN) {
            float4 v = make_float4(acc[i][0], acc[i][1], acc[i][2], acc[i][3]);
            *(float4*)&d_h2[r*32 + tx*4] = v;
        }
    }
}

// ---------------- conv2 per-node logits (warp per node, H=1) ----------------
__global__ void al2_kernel(const float* __restrict__ as2, const float* __restrict__ ad2) {
    int g = blockIdx.x * blockDim.x + threadIdx.x;
    int n = g >> 5, lane = g & 31;
    if (n >= NN) return;
    float h = d_h2[n*32 + lane];
    float ps = h * as2[lane];
    float pd = h * ad2[lane];
#pragma unroll
    for (int m = 1; m <= 16; m <<= 1) {
        ps += __shfl_xor_sync(0xffffffffu, ps, m);
        pd += __shfl_xor_sync(0xffffffffu, pd, m);
    }
    if (lane == 0) { d_als2[n] = ps; d_ald2[n] = pd; }
}

__global__ void alpha2_kernel(const int* __restrict__ ei) {
    int e = blockIdx.x * blockDim.x + threadIdx.x;
    if (e >= NE2) return;
    int s, d;
    if (e < NE) { s = ei[e]; d = ei[NE + e]; } else { s = d = e - NE; }
    float a = lrelu(d_als2[s] + d_ald2[d] + d_ae2[e]);
    d_alpha2[e] = a;
    atomicMax(&d_m2[d], fenc(a));
}

__global__ void expden2_kernel(const int* __restrict__ ei) {
    int e = blockIdx.x * blockDim.x + threadIdx.x;
    if (e >= NE2) return;
    int d = (e < NE) ? ei[NE + e] : (e - NE);
    float v = expf(d_alpha2[e] - fdec(d_m2[d]));
    d_alpha2[e] = v;
    atomicAdd(&d_den2[d], v);
}

// 8 threads per edge (32 channels / float4)
__global__ void msg2_kernel(const int* __restrict__ ei) {
    int g = blockIdx.x * blockDim.x + threadIdx.x;
    int e = g >> 3, part = g & 7;
    if (e >= NE2) return;
    int s, d;
    if (e < NE) { s = ei[e]; d = ei[NE + e]; } else { s = d = e - NE; }
    float w = d_alpha2[e] / (d_den2[d] + 1e-16f);
    float4 hv = *(const float4*)&d_h2[s*32 + part*4];
    float4 m  = make_float4(hv.x*w, hv.y*w, hv.z*w, hv.w*w);
    atomicAdd((float4*)&d_out2[d*32 + part*4], m);
}

// ---------------- global mean pool ----------------
__global__ void pool_kernel(const int* __restrict__ batch, const float* __restrict__ b2) {
    int g = blockIdx.x * blockDim.x + threadIdx.x;
    int n = g >> 5, c = g & 31;
    if (n >= NN) return;
    float v = eluf(d_out2[n*32 + c] + b2[c]);
    int gr = batch[n];
    atomicAdd(&d_gsum[gr*32 + c], v);
    if (c == 0) atomicAdd(&d_gcnt[gr], 1.f);
}

// ---------------- MLP head ----------------
__global__ void head_kernel(const float* __restrict__ W3, const float* __restrict__ b3,
                            const float* __restrict__ W4, const float* __restrict__ b4,
                            float* __restrict__ out) {
    int g = threadIdx.x;
    if (g >= NG) return;
    float gc = fmaxf(d_gcnt[g], 1.f);
    float gv[32];
#pragma unroll
    for (int c = 0; c < 32; c++) gv[c] = d_gsum[g*32 + c] / gc;
    float z[16];
#pragma unroll
    for (int j = 0; j < 16; j++) {
        float s = b3[j];
#pragma unroll
        for (int c = 0; c < 32; c++) s += gv[c] * W3[c*16 + j];
        z[j] = fmaxf(s, 0.f);
    }
#pragma unroll
    for (int o = 0; o < 10; o++) {
        float s = b4[o];
#pragma unroll
        for (int j = 0; j < 16; j++) s += z[j] * W4[j*10 + o];
        out[g*10 + o] = s;
    }
}

// ---------------- launch ----------------
extern "C" void kernel_launch(void* const* d_in, const int* in_sizes, int n_in,
                              void* d_out, int out_size) {
    const float* x     = (const float*)d_in[0];
    const int*   ei    = (const int*)  d_in[1];
    const float* eattr = (const float*)d_in[2];
    const int*   batch = (const int*)  d_in[3];
    const float* W1    = (const float*)d_in[4];
    const float* as1   = (const float*)d_in[5];
    const float* ad1   = (const float*)d_in[6];
    const float* We1   = (const float*)d_in[7];
    const float* ae1w  = (const float*)d_in[8];
    const float* b1    = (const float*)d_in[9];
    const float* W2    = (const float*)d_in[10];
    const float* as2   = (const float*)d_in[11];
    const float* ad2   = (const float*)d_in[12];
    const float* We2   = (const float*)d_in[13];
    const float* ae2w  = (const float*)d_in[14];
    const float* b2    = (const float*)d_in[15];
    const float* W3    = (const float*)d_in[16];
    const float* b3    = (const float*)d_in[17];
    const float* W4    = (const float*)d_in[18];
    const float* b4    = (const float*)d_in[19];
    float* out = (float*)d_out;

    const int TB = 256;
    init_kernel<<<(NN*HD1 + TB - 1)/TB, TB>>>();
    computeM_kernel<<<1, 64>>>(We1, ae1w, We2, ae2w);
    loop_accum_kernel<<<(NE + TB - 1)/TB, TB>>>(ei, eattr);
    gemm1_kernel<<<(NN + 127)/128, 256>>>(x, W1);
    al1_kernel<<<(NN*32 + TB - 1)/TB, TB>>>(as1, ad1);
    ae_edges_kernel<<<(NE + TB - 1)/TB, TB>>>(eattr);
    loop_node_kernel<<<(NN + TB - 1)/TB, TB>>>();
    alpha1_kernel<<<(NE2 + TB - 1)/TB, TB>>>(ei);
    expden1_kernel<<<(NE2 + TB - 1)/TB, TB>>>(ei);
    msg1_kernel<<<((long long)NE2*32 + TB - 1)/TB, TB>>>(ei);
    gemm2_kernel<<<(NN + 127)/128, 256>>>(W2, b1);
    al2_kernel<<<(NN*32 + TB - 1)/TB, TB>>>(as2, ad2);
    alpha2_kernel<<<(NE2 + TB - 1)/TB, TB>>>(ei);
    expden2_kernel<<<(NE2 + TB - 1)/TB, TB>>>(ei);
    msg2_kernel<<<((long long)NE2*8 + TB - 1)/TB, TB>>>(ei);
    pool_kernel<<<(NN*32 + TB - 1)/TB, TB>>>(batch, b2);
    head_kernel<<<1, 64>>>(W3, b3, W4, b4, out);
}

// round 2
// speedup vs baseline: 1.0797x; 1.0797x over previous
#include <cuda_runtime.h>
#include <math.h>

#define NN   50000
#define NE   800000
#define NE2  850000     // NE + NN self loops
#define NG   64
#define IND  128
#define HIDC 32
#define HEADS 4
#define EDIM 8
#define OUTD 10
#define HD1  128        // HEADS*HIDC

// ---------------- scratch (static device globals; no allocation) ----------------
__device__ float    d_loop[NN*EDIM];
__device__ float    d_cnt[NN];
__device__ float    d_h1[NN*HD1];
__device__ float    d_als1[NN*HEADS];
__device__ float    d_ald1[NN*HEADS];
__device__ float    d_alpha1[NE2*HEADS];
__device__ float    d_den1[NN*HEADS];
__device__ float    d_out1[NN*HD1];
__device__ float    d_h2[NN*HIDC];
__device__ float    d_als2[NN];
__device__ float    d_ald2[NN];
__device__ float    d_alpha2[NE2];
__device__ float    d_den2[NN];
__device__ float    d_out2[NN*HIDC];
__device__ float    d_gsum[NG*HIDC];
__device__ float    d_gcnt[NG];
__device__ float    d_M1[EDIM*HEADS];
__device__ float    d_M2[EDIM];

__device__ __forceinline__ float lrelu(float a) { return a > 0.f ? a : 0.2f * a; }
__device__ __forceinline__ float eluf(float a)  { return a > 0.f ? a : expm1f(a); }

// ---------------- init: zero accumulators ----------------
__global__ void init_kernel() {
    int i = blockIdx.x * blockDim.x + threadIdx.x;
    if (i < NN*HD1)   d_out1[i] = 0.f;
    if (i < NN*HIDC)  d_out2[i] = 0.f;
    if (i < NN*EDIM)  d_loop[i] = 0.f;
    if (i < NN*HEADS) d_den1[i] = 0.f;
    if (i < NN)       { d_cnt[i] = 0.f; d_den2[i] = 0.f; }
    if (i < NG*HIDC)  d_gsum[i] = 0.f;
    if (i < NG)       d_gcnt[i] = 0.f;
}

// ---------------- precompute edge-attention projection matrices ----------------
__global__ void computeM_kernel(const float* __restrict__ We1, const float* __restrict__ ae1,
                                const float* __restrict__ We2, const float* __restrict__ ae2) {
    int t = threadIdx.x;
    if (t < 32) {
        int d = t >> 2, h = t & 3;
        float s = 0.f;
        for (int c = 0; c < 32; c++) s += We1[d*128 + h*32 + c] * ae1[h*32 + c];
        d_M1[d*4 + h] = s;
    } else if (t < 40) {
        int d = t - 32;
        float s = 0.f;
        for (int c = 0; c < 32; c++) s += We2[d*32 + c] * ae2[c];
        d_M2[d] = s;
    }
}

// ---------------- self-loop attr accumulation ----------------
__global__ void loop_accum_kernel(const int* __restrict__ ei, const float* __restrict__ eattr) {
    int e = blockIdx.x * blockDim.x + threadIdx.x;
    if (e >= NE) return;
    int d = ei[NE + e];
    atomicAdd(&d_cnt[d], 1.f);
    float4 a = *(const float4*)&eattr[e*8];
    float4 b = *(const float4*)&eattr[e*8 + 4];
    atomicAdd((float4*)&d_loop[d*8], a);
    atomicAdd((float4*)&d_loop[d*8 + 4], b);
}

// ---------------- GEMM1: h1 = x @ W1, fused node-logit epilogue ----------------
__global__ void __launch_bounds__(256) gemm1_kernel(const float* __restrict__ x,
                                                    const float* __restrict__ W1,
                                                    const float* __restrict__ as1,
                                                    const float* __restrict__ ad1) {
    __shared__ float As[16][128];
    __shared__ float Bs[16][128];
    __shared__ float s_as[128], s_ad[128];
    int tid  = threadIdx.x;
    int row0 = blockIdx.x * 128;
    int ty = tid >> 4, tx = tid & 15;
    if (tid < 128) { s_as[tid] = as1[tid]; s_ad[tid] = ad1[tid]; }
    float acc[8][8];
#pragma unroll
    for (int i = 0; i < 8; i++)
#pragma unroll
        for (int j = 0; j < 8; j++) acc[i][j] = 0.f;

    for (int k0 = 0; k0 < 128; k0 += 16) {
        {
            int kk = tid >> 5;
            int j  = (tid & 31) << 2;
            *(float4*)&Bs[kk][j]   = *(const float4*)&W1[(k0+kk)*128 + j];
            *(float4*)&Bs[kk+8][j] = *(const float4*)&W1[(k0+kk+8)*128 + j];
        }
        {
            int rr = tid >> 2;
            int kk = (tid & 3) << 2;
#pragma unroll
            for (int it = 0; it < 2; it++) {
                int r = rr + it*64;
                int grow = row0 + r;
                float4 v = make_float4(0.f,0.f,0.f,0.f);
                if (grow < NN) v = *(const float4*)&x[grow*128 + k0 + kk];
                As[kk+0][r] = v.x; As[kk+1][r] = v.y; As[kk+2][r] = v.z; As[kk+3][r] = v.w;
            }
        }
        __syncthreads();
#pragma unroll
        for (int kk = 0; kk < 16; kk++) {
            float a[8], b[8];
#pragma unroll
            for (int i = 0; i < 8; i++) a[i] = As[kk][ty*8 + i];
#pragma unroll
            for (int j = 0; j < 8; j++) b[j] = Bs[kk][tx*8 + j];
#pragma unroll
            for (int i = 0; i < 8; i++)
#pragma unroll
                for (int j = 0; j < 8; j++) acc[i][j] = fmaf(a[i], b[j], acc[i][j]);
        }
        __syncthreads();
    }
    // store h1
#pragma unroll
    for (int i = 0; i < 8; i++) {
        int r = row0 + ty*8 + i;
        if (r < NN) {
            float4 v0 = make_float4(acc[i][0], acc[i][1], acc[i][2], acc[i][3]);
            float4 v1 = make_float4(acc[i][4], acc[i][5], acc[i][6], acc[i][7]);
            *(float4*)&d_h1[r*128 + tx*8]     = v0;
            *(float4*)&d_h1[r*128 + tx*8 + 4] = v1;
        }
    }
    // fused epilogue: per-node attention logits (als1/ald1)
    float* sred = (float*)As;   // 128 rows x 8 (4 heads x {s,d}) = 1024 floats
    for (int k = tid; k < 1024; k += 256) sred[k] = 0.f;
    __syncthreads();
    int head = tx >> 2;
#pragma unroll
    for (int i = 0; i < 8; i++) {
        float ps = 0.f, pd = 0.f;
#pragma unroll
        for (int j = 0; j < 8; j++) {
            ps = fmaf(acc[i][j], s_as[tx*8 + j], ps);
            pd = fmaf(acc[i][j], s_ad[tx*8 + j], pd);
        }
        atomicAdd(&sred[(ty*8 + i)*8 + head*2 + 0], ps);
        atomicAdd(&sred[(ty*8 + i)*8 + head*2 + 1], pd);
    }
    __syncthreads();
    for (int k = tid; k < 512; k += 256) {
        int r = k >> 2, h = k & 3;
        int grow = row0 + r;
        if (grow < NN) {
            d_als1[grow*4 + h] = sred[r*8 + h*2 + 0];
            d_ald1[grow*4 + h] = sred[r*8 + h*2 + 1];
        }
    }
}

// ---------------- conv1: fused alpha + exp + denominator (no max pass) ----------------
__global__ void alphaden1_kernel(const int* __restrict__ ei, const float* __restrict__ eattr) {
    int e = blockIdx.x * blockDim.x + threadIdx.x;
    if (e >= NE2) return;
    int s, d;
    float ea[8];
    if (e < NE) {
        s = ei[e]; d = ei[NE + e];
        float4 a = *(const float4*)&eattr[e*8];
        float4 b = *(const float4*)&eattr[e*8 + 4];
        ea[0]=a.x; ea[1]=a.y; ea[2]=a.z; ea[3]=a.w;
        ea[4]=b.x; ea[5]=b.y; ea[6]=b.z; ea[7]=b.w;
    } else {
        int n = e - NE; s = d = n;
        float c = fmaxf(d_cnt[n], 1.f);
#pragma unroll
        for (int i = 0; i < 8; i++) ea[i] = d_loop[n*8 + i] / c;
    }
    float4 as = *(const float4*)&d_als1[s*4];
    float4 ad = *(const float4*)&d_ald1[d*4];
    float ae[4];
#pragma unroll
    for (int h = 0; h < 4; h++) {
        float t = 0.f;
#pragma unroll
        for (int i = 0; i < 8; i++) t = fmaf(ea[i], d_M1[i*4 + h], t);
        ae[h] = t;
    }
    float4 v;
    v.x = __expf(lrelu(as.x + ad.x + ae[0]));
    v.y = __expf(lrelu(as.y + ad.y + ae[1]));
    v.z = __expf(lrelu(as.z + ad.z + ae[2]));
    v.w = __expf(lrelu(as.w + ad.w + ae[3]));
    *(float4*)&d_alpha1[e*4] = v;
    atomicAdd(&d_den1[d*4 + 0], v.x);
    atomicAdd(&d_den1[d*4 + 1], v.y);
    atomicAdd(&d_den1[d*4 + 2], v.z);
    atomicAdd(&d_den1[d*4 + 3], v.w);
}

// ---------------- conv1: weighted message scatter (warp per edge) ----------------
__global__ void msg1_kernel(const int* __restrict__ ei) {
    int g = blockIdx.x * blockDim.x + threadIdx.x;
    int e = g >> 5, lane = g & 31;
    if (e >= NE2) return;
    int s, d;
    if (e < NE) { s = ei[e]; d = ei[NE + e]; } else { s = d = e - NE; }
    float wv = 0.f;
    if (lane < 4) wv = d_alpha1[e*4 + lane] / (d_den1[d*4 + lane] + 1e-16f);
    float w = __shfl_sync(0xffffffffu, wv, lane >> 3);
    float4 hv = *(const float4*)&d_h1[s*128 + lane*4];
    float4 m  = make_float4(hv.x*w, hv.y*w, hv.z*w, hv.w*w);
    atomicAdd((float4*)&d_out1[d*128 + lane*4], m);
}

// ---------------- GEMM2: h2 = elu(out1 + b1) @ W2, fused logit epilogue ----------------
__global__ void __launch_bounds__(256) gemm2_kernel(const float* __restrict__ W2,
                                                    const float* __restrict__ b1,
                                                    const float* __restrict__ as2,
                                                    const float* __restrict__ ad2) {
    __shared__ float As[32][128];
    __shared__ float Bs[32][32];
    __shared__ float s_as[32], s_ad[32];
    int tid  = threadIdx.x;
    int row0 = blockIdx.x * 128;
    int ty = tid >> 3, tx = tid & 7;
    if (tid < 32) { s_as[tid] = as2[tid]; s_ad[tid] = ad2[tid]; }
    float acc[4][4];
#pragma unroll
    for (int i = 0; i < 4; i++)
#pragma unroll
        for (int j = 0; j < 4; j++) acc[i][j] = 0.f;

    for (int k0 = 0; k0 < 128; k0 += 32) {
        {
            int kk = tid >> 3, j = (tid & 7) << 2;
            *(float4*)&Bs[kk][j] = *(const float4*)&W2[(k0+kk)*32 + j];
        }
        {
            int rr = tid >> 3;
            int kks = (tid & 7) << 2;
            float4 bb = *(const float4*)&b1[k0 + kks];
#pragma unroll
            for (int it = 0; it < 4; it++) {
                int r = rr + it*32;
                int grow = row0 + r;
                float4 v = make_float4(0.f,0.f,0.f,0.f);
                if (grow < NN) {
                    v = *(const float4*)&d_out1[grow*128 + k0 + kks];
                    v.x = eluf(v.x + bb.x); v.y = eluf(v.y + bb.y);
                    v.z = eluf(v.z + bb.z); v.w = eluf(v.w + bb.w);
                }
                As[kks+0][r] = v.x; As[kks+1][r] = v.y; As[kks+2][r] = v.z; As[kks+3][r] = v.w;
            }
        }
        __syncthreads();
#pragma unroll
        for (int kk = 0; kk < 32; kk++) {
            float a[4], b[4];
#pragma unroll
            for (int i = 0; i < 4; i++) a[i] = As[kk][ty*4 + i];
#pragma unroll
            for (int j = 0; j < 4; j++) b[j] = Bs[kk][tx*4 + j];
#pragma unroll
            for (int i = 0; i < 4; i++)
#pragma unroll
                for (int j = 0; j < 4; j++) acc[i][j] = fmaf(a[i], b[j], acc[i][j]);
        }
        __syncthreads();
    }
#pragma unroll
    for (int i = 0; i < 4; i++) {
        int r = row0 + ty*4 + i;
        if (r < NN) {
            float4 v = make_float4(acc[i][0], acc[i][1], acc[i][2], acc[i][3]);
            *(float4*)&d_h2[r*32 + tx*4] = v;
        }
    }
    // fused epilogue: als2/ald2
    float* sred = (float*)As;   // 128 rows x 2
    for (int k = tid; k < 256; k += 256) sred[k] = 0.f;
    __syncthreads();
#pragma unroll
    for (int i = 0; i < 4; i++) {
        float ps = 0.f, pd = 0.f;
#pragma unroll
        for (int j = 0; j < 4; j++) {
            ps = fmaf(acc[i][j], s_as[tx*4 + j], ps);
            pd = fmaf(acc[i][j], s_ad[tx*4 + j], pd);
        }
        atomicAdd(&sred[(ty*4 + i)*2 + 0], ps);
        atomicAdd(&sred[(ty*4 + i)*2 + 1], pd);
    }
    __syncthreads();
    for (int k = tid; k < 128; k += 256) {
        int grow = row0 + k;
        if (grow < NN) {
            d_als2[grow] = sred[k*2 + 0];
            d_ald2[grow] = sred[k*2 + 1];
        }
    }
}

// ---------------- conv2: fused alpha + exp + denom ----------------
__global__ void alphaden2_kernel(const int* __restrict__ ei, const float* __restrict__ eattr) {
    int e = blockIdx.x * blockDim.x + threadIdx.x;
    if (e >= NE2) return;
    int s, d;
    float ea[8];
    if (e < NE) {
        s = ei[e]; d = ei[NE + e];
        float4 a = *(const float4*)&eattr[e*8];
        float4 b = *(const float4*)&eattr[e*8 + 4];
        ea[0]=a.x; ea[1]=a.y; ea[2]=a.z; ea[3]=a.w;
        ea[4]=b.x; ea[5]=b.y; ea[6]=b.z; ea[7]=b.w;
    } else {
        int n = e - NE; s = d = n;
        float c = fmaxf(d_cnt[n], 1.f);
#pragma unroll
        for (int i = 0; i < 8; i++) ea[i] = d_loop[n*8 + i] / c;
    }
    float ae = 0.f;
#pragma unroll
    for (int i = 0; i < 8; i++) ae = fmaf(ea[i], d_M2[i], ae);
    float a = __expf(lrelu(d_als2[s] + d_ald2[d] + ae));
    d_alpha2[e] = a;
    atomicAdd(&d_den2[d], a);
}

// ---------------- conv2 message scatter (8 threads per edge) ----------------
__global__ void msg2_kernel(const int* __restrict__ ei) {
    int g = blockIdx.x * blockDim.x + threadIdx.x;
    int e = g >> 3, part = g & 7;
    if (e >= NE2) return;
    int s, d;
    if (e < NE) { s = ei[e]; d = ei[NE + e]; } else { s = d = e - NE; }
    float w = 0.f;
    if (part == 0) w = d_alpha2[e] / (d_den2[d] + 1e-16f);
    w = __shfl_sync(0xffffffffu, w, 0, 8);
    float4 hv = *(const float4*)&d_h2[s*32 + part*4];
    float4 m  = make_float4(hv.x*w, hv.y*w, hv.z*w, hv.w*w);
    atomicAdd((float4*)&d_out2[d*32 + part*4], m);
}

// ---------------- global mean pool ----------------
__global__ void pool_kernel(const int* __restrict__ batch, const float* __restrict__ b2) {
    int g = blockIdx.x * blockDim.x + threadIdx.x;
    int n = g >> 5, c = g & 31;
    if (n >= NN) return;
    float v = eluf(d_out2[n*32 + c] + b2[c]);
    int gr = batch[n];
    atomicAdd(&d_gsum[gr*32 + c], v);
    if (c == 0) atomicAdd(&d_gcnt[gr], 1.f);
}

// ---------------- MLP head ----------------
__global__ void head_kernel(const float* __restrict__ W3, const float* __restrict__ b3,
                            const float* __restrict__ W4, const float* __restrict__ b4,
                            float* __restrict__ out) {
    int g = threadIdx.x;
    if (g >= NG) return;
    float gc = fmaxf(d_gcnt[g], 1.f);
    float gv[32];
#pragma unroll
    for (int c = 0; c < 32; c++) gv[c] = d_gsum[g*32 + c] / gc;
    float z[16];
#pragma unroll
    for (int j = 0; j < 16; j++) {
        float s = b3[j];
#pragma unroll
        for (int c = 0; c < 32; c++) s += gv[c] * W3[c*16 + j];
        z[j] = fmaxf(s, 0.f);
    }
#pragma unroll
    for (int o = 0; o < 10; o++) {
        float s = b4[o];
#pragma unroll
        for (int j = 0; j < 16; j++) s += z[j] * W4[j*10 + o];
        out[g*10 + o] = s;
    }
}

// ---------------- launch ----------------
extern "C" void kernel_launch(void* const* d_in, const int* in_sizes, int n_in,
                              void* d_out, int out_size) {
    const float* x     = (const float*)d_in[0];
    const int*   ei    = (const int*)  d_in[1];
    const float* eattr = (const float*)d_in[2];
    const int*   batch = (const int*)  d_in[3];
    const float* W1    = (const float*)d_in[4];
    const float* as1   = (const float*)d_in[5];
    const float* ad1   = (const float*)d_in[6];
    const float* We1   = (const float*)d_in[7];
    const float* ae1w  = (const float*)d_in[8];
    const float* b1    = (const float*)d_in[9];
    const float* W2    = (const float*)d_in[10];
    const float* as2   = (const float*)d_in[11];
    const float* ad2   = (const float*)d_in[12];
    const float* We2   = (const float*)d_in[13];
    const float* ae2w  = (const float*)d_in[14];
    const float* b2    = (const float*)d_in[15];
    const float* W3    = (const float*)d_in[16];
    const float* b3    = (const float*)d_in[17];
    const float* W4    = (const float*)d_in[18];
    const float* b4    = (const float*)d_in[19];
    float* out = (float*)d_out;

    const int TB = 256;
    init_kernel<<<(NN*HD1 + TB - 1)/TB, TB>>>();
    computeM_kernel<<<1, 64>>>(We1, ae1w, We2, ae2w);
    loop_accum_kernel<<<(NE + TB - 1)/TB, TB>>>(ei, eattr);
    gemm1_kernel<<<(NN + 127)/128, 256>>>(x, W1, as1, ad1);
    alphaden1_kernel<<<(NE2 + TB - 1)/TB, TB>>>(ei, eattr);
    msg1_kernel<<<((long long)NE2*32 + TB - 1)/TB, TB>>>(ei);
    gemm2_kernel<<<(NN + 127)/128, 256>>>(W2, b1, as2, ad2);
    alphaden2_kernel<<<(NE2 + TB - 1)/TB, TB>>>(ei, eattr);
    msg2_kernel<<<((long long)NE2*8 + TB - 1)/TB, TB>>>(ei);
    pool_kernel<<<(NN*32 + TB - 1)/TB, TB>>>(batch, b2);
    head_kernel<<<1, 64>>>(W3, b3, W4, b4, out);
}